// round 7
// baseline (speedup 1.0000x reference)
#include <cuda_runtime.h>
#include <math.h>
#include <stdint.h>

// ---------------------------------------------------------------------------
// Problem: B=4, T=1024, C=1024, H=16, Dh=64, D_FF=4096, WINDOW=256. M=4096.
// ---------------------------------------------------------------------------
#define TOKENS 4096
#define CDIM   1024
#define FFDIM  4096
#define WIN    256

__device__ float g_qkv[TOKENS * 3 * CDIM];
__device__ float g_ctx[TOKENS * CDIM];     // tf32-rounded at write
__device__ float g_y[TOKENS * CDIM];
__device__ float g_x1[TOKENS * CDIM];      // exact (residual use)
__device__ float g_x1r[TOKENS * CDIM];     // tf32-rounded (GEMM input)
__device__ float g_h[TOKENS * FFDIM];      // tf32-rounded at write (GELU out)
__device__ float g_xr[TOKENS * CDIM];      // tf32-rounded copy of x
__device__ float g_wqkvr[3 * CDIM * CDIM];
__device__ float g_wor[CDIM * CDIM];
__device__ float g_w1r[FFDIM * CDIM];
__device__ float g_w2r[CDIM * FFDIM];

// ---------------------------------------------------------------------------
// helpers
// ---------------------------------------------------------------------------
__device__ __forceinline__ uint32_t smem_u32(const void* p) {
    uint32_t a;
    asm("{ .reg .u64 t; cvta.to.shared.u64 t, %1; cvt.u32.u64 %0, t; }"
        : "=r"(a) : "l"(p));
    return a;
}

#define CP_ASYNC16(sa, ga) \
    asm volatile("cp.async.cg.shared.global [%0], [%1], 16;" :: "r"((uint32_t)(sa)), "l"(ga))
#define CP_COMMIT() asm volatile("cp.async.commit_group;" ::: "memory")
#define CP_WAIT(n)  asm volatile("cp.async.wait_group %0;" :: "n"(n) : "memory")

__device__ __forceinline__ float round_tf32(float f) {
    uint32_t u;
    asm("cvt.rna.tf32.f32 %0, %1;" : "=r"(u) : "f"(f));
    return __uint_as_float(u);
}

__device__ __forceinline__ void mma_tf32(float* d,
                                         uint32_t a0, uint32_t a1,
                                         uint32_t a2, uint32_t a3,
                                         uint32_t b0, uint32_t b1) {
    asm volatile(
        "mma.sync.aligned.m16n8k8.row.col.f32.tf32.tf32.f32 "
        "{%0,%1,%2,%3}, {%4,%5,%6,%7}, {%8,%9}, {%0,%1,%2,%3};"
        : "+f"(d[0]), "+f"(d[1]), "+f"(d[2]), "+f"(d[3])
        : "r"(a0), "r"(a1), "r"(a2), "r"(a3), "r"(b0), "r"(b1));
}

__device__ __forceinline__ float gelu_exact(float v) {
    return 0.5f * v * (1.0f + erff(v * 0.70710678118654752f));
}

// ---------------------------------------------------------------------------
// fused tf32 rounding pass over 5 buffers (one launch)
// ---------------------------------------------------------------------------
__global__ void __launch_bounds__(256) round_all_kernel(
    const float4* __restrict__ i0, float4* __restrict__ o0, int n0,
    const float4* __restrict__ i1, float4* __restrict__ o1, int n1,
    const float4* __restrict__ i2, float4* __restrict__ o2, int n2,
    const float4* __restrict__ i3, float4* __restrict__ o3, int n3,
    const float4* __restrict__ i4, float4* __restrict__ o4, int n4)
{
    const int total = n0 + n1 + n2 + n3 + n4;
    const int stride = gridDim.x * 256;
    for (int i = blockIdx.x * 256 + threadIdx.x; i < total; i += stride) {
        const float4* src;
        float4* dst;
        int idx = i;
        if (idx < n0)                    { src = i0; dst = o0; }
        else if ((idx -= n0) < n1)       { src = i1; dst = o1; }
        else if ((idx -= n1) < n2)       { src = i2; dst = o2; }
        else if ((idx -= n2) < n3)       { src = i3; dst = o3; }
        else            { idx -= n3;       src = i4; dst = o4; }
        float4 v = src[idx];
        v.x = round_tf32(v.x); v.y = round_tf32(v.y);
        v.z = round_tf32(v.z); v.w = round_tf32(v.w);
        dst[idx] = v;
    }
}

// ---------------------------------------------------------------------------
// tf32 mma.sync GEMM (inputs pre-rounded; no in-loop cvt)
// CTA 128x128xBK32, 8 warps (4m x 2n), warp tile 32x64, m16n8k8.
// 2-stage cp.async double buffer; GSTRIDE=48 -> conflict-free LDS.128.
// KDIM templated: compile-time strides, incremental global pointers.
// MMA order: s -> ni -> mi, 8 independent MMAs between same-acc writes.
// 96KB smem/CTA -> 2 CTAs/SM.
// ---------------------------------------------------------------------------
#define GBM 128
#define GBN 128
#define GBK 32
#define GSTRIDE 48
#define GSTG_FLOATS ((GBM + GBN) * GSTRIDE)     // 12288 floats / stage
#define GEMM_SMEM (2 * GSTG_FLOATS * 4)         // 98304 bytes

template <bool GELU, bool RESID, bool ROUND, int KDIM>
__global__ void __launch_bounds__(256) tgemm(
    const float* __restrict__ A, const float* __restrict__ B,
    const float* __restrict__ bias, const float* __restrict__ resid,
    float* __restrict__ C, int N)
{
    extern __shared__ float sm[];
    const int tid  = threadIdx.x;
    const int wid  = tid >> 5, lane = tid & 31;
    const int wm   = wid >> 1, wn = wid & 1;     // 4 x 2 warp grid
    const int g    = lane >> 2, tg = lane & 3;
    const int m0   = blockIdx.y * GBM;
    const int n0   = blockIdx.x * GBN;
    constexpr int NITER = KDIM / GBK;
    static_assert(NITER % 2 == 0, "NITER even");

    float acc[2][8][4];
    #pragma unroll
    for (int i = 0; i < 2; i++)
        #pragma unroll
        for (int j = 0; j < 8; j++)
            #pragma unroll
            for (int k = 0; k < 4; k++) acc[i][j][k] = 0.f;

    // loader lanes
    const int lr = tid >> 3;            // 0..31
    const int lc = (tid & 7) * 4;       // 0..28
    const float* aptr = A + (size_t)(m0 + lr) * KDIM + lc;
    const float* bptr = B + (size_t)(n0 + lr) * KDIM + lc;
    const uint32_t sa_st = smem_u32(sm) + (uint32_t)(lr * GSTRIDE + lc) * 4u;
    const uint32_t sb_st = sa_st + GBM * GSTRIDE * 4u;
    constexpr uint32_t STG_B = GSTG_FLOATS * 4u;   // stage byte offset

    auto load_chunk = [&](uint32_t stoff) {
        #pragma unroll
        for (int i = 0; i < 4; i++)
            CP_ASYNC16(sa_st + stoff + i * (32 * GSTRIDE * 4),
                       aptr + (size_t)i * 32 * KDIM);
        #pragma unroll
        for (int i = 0; i < 4; i++)
            CP_ASYNC16(sb_st + stoff + i * (32 * GSTRIDE * 4),
                       bptr + (size_t)i * 32 * KDIM);
        aptr += GBK; bptr += GBK;
    };

    // per-warp fragment base pointers (stage 0)
    const float* sAg = sm + (wm * 32 + g) * GSTRIDE + 4 * tg;
    const float* sBg = sm + GBM * GSTRIDE + (wn * 64 + g) * GSTRIDE + 4 * tg;

    auto compute = [&](int stf) {   // stf = stage float offset (compile-time 0 / GSTG_FLOATS)
        const float* sA = sAg + stf;
        const float* sB = sBg + stf;
        #pragma unroll
        for (int half = 0; half < 2; half++) {
            const int kb = half * 16;
            uint4 alo[2], ahi[2];
            #pragma unroll
            for (int mi = 0; mi < 2; mi++) {
                alo[mi] = *(const uint4*)&sA[(mi * 16) * GSTRIDE + kb];
                ahi[mi] = *(const uint4*)&sA[(mi * 16 + 8) * GSTRIDE + kb];
            }
            #pragma unroll
            for (int grp = 0; grp < 2; grp++) {
                uint4 bv[4];
                #pragma unroll
                for (int nn = 0; nn < 4; nn++)
                    bv[nn] = *(const uint4*)&sB[((grp * 4 + nn) * 8) * GSTRIDE + kb];
                // s = 0 sweep (8 independent MMAs)
                #pragma unroll
                for (int nn = 0; nn < 4; nn++)
                    #pragma unroll
                    for (int mi = 0; mi < 2; mi++)
                        mma_tf32(acc[mi][grp * 4 + nn],
                                 alo[mi].x, ahi[mi].x, alo[mi].y, ahi[mi].y,
                                 bv[nn].x, bv[nn].y);
                // s = 1 sweep
                #pragma unroll
                for (int nn = 0; nn < 4; nn++)
                    #pragma unroll
                    for (int mi = 0; mi < 2; mi++)
                        mma_tf32(acc[mi][grp * 4 + nn],
                                 alo[mi].z, ahi[mi].z, alo[mi].w, ahi[mi].w,
                                 bv[nn].z, bv[nn].w);
            }
        }
    };

    load_chunk(0); CP_COMMIT();

    #pragma unroll 1
    for (int j = 0; j < NITER; j += 2) {
        // chunk j in stage0; load j+1 into stage1
        load_chunk(STG_B); CP_COMMIT();
        CP_WAIT(1);
        __syncthreads();
        compute(0);
        __syncthreads();
        // chunk j+1 in stage1; load j+2 into stage0 (if any)
        if (j + 2 < NITER) load_chunk(0);
        CP_COMMIT();
        CP_WAIT(1);
        __syncthreads();
        compute(GSTG_FLOATS);
        __syncthreads();
    }

    // epilogue
    #pragma unroll
    for (int mi = 0; mi < 2; mi++) {
        #pragma unroll
        for (int rr = 0; rr < 2; rr++) {
            const int m = m0 + wm * 32 + mi * 16 + rr * 8 + g;
            float* crow = C + (size_t)m * N;
            const float* rrow = RESID ? (resid + (size_t)m * N) : nullptr;
            #pragma unroll
            for (int ni = 0; ni < 8; ni++) {
                const int n = n0 + wn * 64 + ni * 8 + 2 * tg;
                float ox = acc[mi][ni][rr * 2 + 0] + bias[n];
                float oy = acc[mi][ni][rr * 2 + 1] + bias[n + 1];
                if (RESID) { ox += rrow[n]; oy += rrow[n + 1]; }
                if (GELU)  { ox = gelu_exact(ox); oy = gelu_exact(oy); }
                if (ROUND) { ox = round_tf32(ox); oy = round_tf32(oy); }
                float2 o = make_float2(ox, oy);
                *(float2*)(crow + n) = o;
            }
        }
    }
}

// ---------------------------------------------------------------------------
// Banded causal attention, flash-style (fp32 SIMT). Output tf32-rounded.
// ---------------------------------------------------------------------------
#define QPAD 65
#define ATTN_SMEM ((3 * 64 * QPAD + 64 * 64 + 3 * 64 + 256) * 4)

__global__ void __launch_bounds__(256) attn_kernel(
    const float* __restrict__ qkv, float* __restrict__ ctx)
{
    extern __shared__ float smf[];
    float* Qs    = smf;
    float* Ks    = Qs + 64 * QPAD;
    float* Ps    = Ks + 64 * QPAD;
    float* Vs    = Ps + 64 * QPAD;
    float* row_m = Vs + 64 * 64;
    float* row_l = row_m + 64;
    float* row_a = row_l + 64;
    float* red   = row_a + 64;

    const int t  = threadIdx.x;
    const int bh = blockIdx.y;
    const int b  = bh >> 4, h = bh & 15;
    const int q0 = blockIdx.x * 64;
    const size_t base = (size_t)b * 1024 * 3072 + (size_t)h * 64;

    {
        const int r = t >> 2, c = (t & 3) * 16;
        #pragma unroll
        for (int cc = 0; cc < 16; cc += 4) {
            float4 v = *(const float4*)(qkv + base + (size_t)(q0 + r) * 3072 + c + cc);
            Qs[r * QPAD + c + cc + 0] = v.x * 0.125f;
            Qs[r * QPAD + c + cc + 1] = v.y * 0.125f;
            Qs[r * QPAD + c + cc + 2] = v.z * 0.125f;
            Qs[r * QPAD + c + cc + 3] = v.w * 0.125f;
        }
    }
    if (t < 64) { row_m[t] = -1e30f; row_l[t] = 0.f; }

    float acc[4][4];
    #pragma unroll
    for (int i = 0; i < 4; i++)
        #pragma unroll
        for (int j = 0; j < 4; j++) acc[i][j] = 0.f;

    const int qs = (t & 15) * 4;
    const int ds = (t >> 4) * 4;
    const int iq = (t >> 4) * 4;
    const int jk = (t & 15) * 4;
    const int i_row = t & 63, grp = t >> 6;

    const int kt_lo = (q0 >= WIN) ? ((q0 - (WIN - 1)) >> 6) : 0;
    const int kt_hi = q0 >> 6;

    for (int kt = kt_lo; kt <= kt_hi; kt++) {
        const int k0 = kt * 64;
        __syncthreads();
        {
            const int r = t >> 2, c = (t & 3) * 16;
            #pragma unroll
            for (int cc = 0; cc < 16; cc += 4) {
                float4 kv = *(const float4*)(qkv + base + (size_t)(k0 + r) * 3072 + 1024 + c + cc);
                Ks[r * QPAD + c + cc + 0] = kv.x;
                Ks[r * QPAD + c + cc + 1] = kv.y;
                Ks[r * QPAD + c + cc + 2] = kv.z;
                Ks[r * QPAD + c + cc + 3] = kv.w;
                float4 vv = *(const float4*)(qkv + base + (size_t)(k0 + r) * 3072 + 2048 + c + cc);
                *(float4*)&Vs[r * 64 + c + cc] = vv;
            }
        }
        __syncthreads();

        float s[4][4];
        #pragma unroll
        for (int i = 0; i < 4; i++)
            #pragma unroll
            for (int j = 0; j < 4; j++) s[i][j] = 0.f;
        #pragma unroll 8
        for (int d = 0; d < 64; d++) {
            float qf[4], kf[4];
            #pragma unroll
            for (int ii = 0; ii < 4; ii++) qf[ii] = Qs[(iq + ii) * QPAD + d];
            #pragma unroll
            for (int jj = 0; jj < 4; jj++) kf[jj] = Ks[(jk + jj) * QPAD + d];
            #pragma unroll
            for (int ii = 0; ii < 4; ii++)
                #pragma unroll
                for (int jj = 0; jj < 4; jj++)
                    s[ii][jj] = fmaf(qf[ii], kf[jj], s[ii][jj]);
        }
        #pragma unroll
        for (int ii = 0; ii < 4; ii++) {
            const int qi = q0 + iq + ii;
            #pragma unroll
            for (int jj = 0; jj < 4; jj++) {
                const int kj = k0 + jk + jj;
                const bool ok = (kj <= qi) && (qi - kj < WIN);
                Ps[(iq + ii) * QPAD + jk + jj] = ok ? s[ii][jj] : -1e30f;
            }
        }
        __syncthreads();

        {
            float pm = -1e30f;
            #pragma unroll
            for (int jj = 0; jj < 16; jj++)
                pm = fmaxf(pm, Ps[i_row * QPAD + grp * 16 + jj]);
            red[i_row * 4 + grp] = pm;
        }
        __syncthreads();
        if (t < 64) {
            const float mo = row_m[t];
            float mx = fmaxf(fmaxf(red[t * 4 + 0], red[t * 4 + 1]),
                             fmaxf(red[t * 4 + 2], red[t * 4 + 3]));
            mx = fmaxf(mx, mo);
            row_a[t] = expf(mo - mx);
            row_m[t] = mx;
        }
        __syncthreads();
        {
            const float m = row_m[i_row];
            float psum = 0.f;
            #pragma unroll
            for (int jj = 0; jj < 16; jj++) {
                const float sv = Ps[i_row * QPAD + grp * 16 + jj];
                const float p = (sv > -1e29f) ? expf(sv - m) : 0.f;
                Ps[i_row * QPAD + grp * 16 + jj] = p;
                psum += p;
            }
            red[i_row * 4 + grp] = psum;
        }
        __syncthreads();
        if (t < 64)
            row_l[t] = row_l[t] * row_a[t] +
                       red[t * 4 + 0] + red[t * 4 + 1] + red[t * 4 + 2] + red[t * 4 + 3];

        float al[4];
        #pragma unroll
        for (int qq = 0; qq < 4; qq++) al[qq] = row_a[qs + qq];
        #pragma unroll
        for (int qq = 0; qq < 4; qq++)
            #pragma unroll
            for (int dd = 0; dd < 4; dd++) acc[qq][dd] *= al[qq];

        #pragma unroll 8
        for (int jj = 0; jj < 64; jj++) {
            float4 v4 = *(const float4*)&Vs[jj * 64 + ds];
            float pf[4];
            #pragma unroll
            for (int qq = 0; qq < 4; qq++) pf[qq] = Ps[(qs + qq) * QPAD + jj];
            #pragma unroll
            for (int qq = 0; qq < 4; qq++) {
                acc[qq][0] = fmaf(pf[qq], v4.x, acc[qq][0]);
                acc[qq][1] = fmaf(pf[qq], v4.y, acc[qq][1]);
                acc[qq][2] = fmaf(pf[qq], v4.z, acc[qq][2]);
                acc[qq][3] = fmaf(pf[qq], v4.w, acc[qq][3]);
            }
        }
    }

    __syncthreads();
    #pragma unroll
    for (int qq = 0; qq < 4; qq++) {
        const float inv = 1.f / row_l[qs + qq];
        float4 o;
        o.x = round_tf32(acc[qq][0] * inv);
        o.y = round_tf32(acc[qq][1] * inv);
        o.z = round_tf32(acc[qq][2] * inv);
        o.w = round_tf32(acc[qq][3] * inv);
        *(float4*)(ctx + (size_t)(b * 1024 + q0 + qs + qq) * 1024 + h * 64 + ds) = o;
    }
}

// ---------------------------------------------------------------------------
// LayerNorm: optional second tf32-rounded output
// ---------------------------------------------------------------------------
__global__ void __launch_bounds__(256) ln_kernel(
    const float* __restrict__ in, const float* __restrict__ g,
    const float* __restrict__ be, float* __restrict__ out,
    float* __restrict__ out_r)
{
    __shared__ float red[8];
    __shared__ float s_mu, s_rs;
    const int t = threadIdx.x;
    const size_t row = blockIdx.x;

    float4 v = ((const float4*)(in + row * 1024))[t];
    float sum = v.x + v.y + v.z + v.w;
    #pragma unroll
    for (int o = 16; o; o >>= 1) sum += __shfl_xor_sync(~0u, sum, o);
    if ((t & 31) == 0) red[t >> 5] = sum;
    __syncthreads();
    if (t == 0) {
        float s = 0.f;
        #pragma unroll
        for (int i = 0; i < 8; i++) s += red[i];
        s_mu = s * (1.f / 1024.f);
    }
    __syncthreads();
    const float mu = s_mu;
    const float dx = v.x - mu, dy = v.y - mu, dz = v.z - mu, dw = v.w - mu;
    float sq = dx * dx + dy * dy + dz * dz + dw * dw;
    #pragma unroll
    for (int o = 16; o; o >>= 1) sq += __shfl_xor_sync(~0u, sq, o);
    __syncthreads();
    if ((t & 31) == 0) red[t >> 5] = sq;
    __syncthreads();
    if (t == 0) {
        float s = 0.f;
        #pragma unroll
        for (int i = 0; i < 8; i++) s += red[i];
        s_rs = rsqrtf(s * (1.f / 1024.f) + 1e-5f);
    }
    __syncthreads();
    const float rs = s_rs;
    float4 gv = ((const float4*)g)[t];
    float4 bv = ((const float4*)be)[t];
    float4 o;
    o.x = dx * rs * gv.x + bv.x;
    o.y = dy * rs * gv.y + bv.y;
    o.z = dz * rs * gv.z + bv.z;
    o.w = dw * rs * gv.w + bv.w;
    ((float4*)(out + row * 1024))[t] = o;
    if (out_r) {
        float4 r;
        r.x = round_tf32(o.x); r.y = round_tf32(o.y);
        r.z = round_tf32(o.z); r.w = round_tf32(o.w);
        ((float4*)(out_r + row * 1024))[t] = r;
    }
}

// ---------------------------------------------------------------------------
// launch
// ---------------------------------------------------------------------------
extern "C" void kernel_launch(void* const* d_in, const int* in_sizes, int n_in,
                              void* d_out, int out_size)
{
    const float* x    = (const float*)d_in[0];
    const float* Wqkv = (const float*)d_in[1];
    const float* bqkv = (const float*)d_in[2];
    const float* Wo   = (const float*)d_in[3];
    const float* bo   = (const float*)d_in[4];
    const float* W1   = (const float*)d_in[5];
    const float* b1   = (const float*)d_in[6];
    const float* W2   = (const float*)d_in[7];
    const float* b2   = (const float*)d_in[8];
    const float* g1   = (const float*)d_in[9];
    const float* be1  = (const float*)d_in[10];
    const float* g2   = (const float*)d_in[11];
    const float* be2  = (const float*)d_in[12];
    float* out = (float*)d_out;

    float *qkv, *ctx, *y, *x1, *x1r, *hb, *xr, *wqkvr, *wor, *w1r, *w2r;
    cudaGetSymbolAddress((void**)&qkv,   g_qkv);
    cudaGetSymbolAddress((void**)&ctx,   g_ctx);
    cudaGetSymbolAddress((void**)&y,     g_y);
    cudaGetSymbolAddress((void**)&x1,    g_x1);
    cudaGetSymbolAddress((void**)&x1r,   g_x1r);
    cudaGetSymbolAddress((void**)&hb,    g_h);
    cudaGetSymbolAddress((void**)&xr,    g_xr);
    cudaGetSymbolAddress((void**)&wqkvr, g_wqkvr);
    cudaGetSymbolAddress((void**)&wor,   g_wor);
    cudaGetSymbolAddress((void**)&w1r,   g_w1r);
    cudaGetSymbolAddress((void**)&w2r,   g_w2r);

    cudaFuncSetAttribute(attn_kernel,
                         cudaFuncAttributeMaxDynamicSharedMemorySize, ATTN_SMEM);
    cudaFuncSetAttribute((tgemm<false, false, false, 1024>),
                         cudaFuncAttributeMaxDynamicSharedMemorySize, GEMM_SMEM);
    cudaFuncSetAttribute((tgemm<false, true, false, 1024>),
                         cudaFuncAttributeMaxDynamicSharedMemorySize, GEMM_SMEM);
    cudaFuncSetAttribute((tgemm<true, false, true, 1024>),
                         cudaFuncAttributeMaxDynamicSharedMemorySize, GEMM_SMEM);
    cudaFuncSetAttribute((tgemm<false, true, false, 4096>),
                         cudaFuncAttributeMaxDynamicSharedMemorySize, GEMM_SMEM);

    dim3 thr(256);

    // 0) pre-round all GEMM inputs to tf32 bit patterns (single fused launch)
    round_all_kernel<<<2048, thr>>>(
        (const float4*)x,    (float4*)xr,    TOKENS * CDIM / 4,
        (const float4*)Wqkv, (float4*)wqkvr, 3 * CDIM * CDIM / 4,
        (const float4*)Wo,   (float4*)wor,   CDIM * CDIM / 4,
        (const float4*)W1,   (float4*)w1r,   FFDIM * CDIM / 4,
        (const float4*)W2,   (float4*)w2r,   CDIM * FFDIM / 4);

    // 1) QKV projection
    tgemm<false, false, false, 1024><<<dim3(3072 / GBN, TOKENS / GBM), thr, GEMM_SMEM>>>(
        xr, wqkvr, bqkv, nullptr, qkv, 3 * CDIM);
    // 2) banded attention (writes tf32-rounded ctx)
    attn_kernel<<<dim3(1024 / 64, 4 * 16), thr, ATTN_SMEM>>>(qkv, ctx);
    // 3) Wo + bias + residual(x exact)
    tgemm<false, true, false, 1024><<<dim3(CDIM / GBN, TOKENS / GBM), thr, GEMM_SMEM>>>(
        ctx, wor, bo, x, y, CDIM);
    // 4) LN1 -> x1 (exact) + x1r (rounded)
    ln_kernel<<<TOKENS, thr>>>(y, g1, be1, x1, x1r);
    // 5) W1 + bias + GELU (writes tf32-rounded h)
    tgemm<true, false, true, 1024><<<dim3(FFDIM / GBN, TOKENS / GBM), thr, GEMM_SMEM>>>(
        x1r, w1r, b1, nullptr, hb, FFDIM);
    // 6) W2 + bias + residual(x1 exact)
    tgemm<false, true, false, 4096><<<dim3(CDIM / GBN, TOKENS / GBM), thr, GEMM_SMEM>>>(
        hb, w2r, b2, x1, y, CDIM);
    // 7) LN2 -> out
    ln_kernel<<<TOKENS, thr>>>(y, g2, be2, out, nullptr);
}

// round 8
// speedup vs baseline: 1.0722x; 1.0722x over previous
#include <cuda_runtime.h>
#include <math.h>
#include <stdint.h>

// ---------------------------------------------------------------------------
// Problem: B=4, T=1024, C=1024, H=16, Dh=64, D_FF=4096, WINDOW=256. M=4096.
// ---------------------------------------------------------------------------
#define TOKENS 4096
#define CDIM   1024
#define FFDIM  4096
#define WIN    256

__device__ float g_qkv[TOKENS * 3 * CDIM];
__device__ float g_ctx[TOKENS * CDIM];     // tf32-rounded at write
__device__ float g_y[TOKENS * CDIM];
__device__ float g_x1[TOKENS * CDIM];      // exact (residual use)
__device__ float g_x1r[TOKENS * CDIM];     // tf32-rounded (GEMM input)
__device__ float g_h[TOKENS * FFDIM];      // tf32-rounded at write (GELU out)
__device__ float g_xr[TOKENS * CDIM];      // tf32-rounded copy of x
__device__ float g_wqkvr[3 * CDIM * CDIM];
__device__ float g_wor[CDIM * CDIM];
__device__ float g_w1r[FFDIM * CDIM];
__device__ float g_w2r[CDIM * FFDIM];

// ---------------------------------------------------------------------------
// helpers
// ---------------------------------------------------------------------------
__device__ __forceinline__ uint32_t smem_u32(const void* p) {
    uint32_t a;
    asm("{ .reg .u64 t; cvta.to.shared.u64 t, %1; cvt.u32.u64 %0, t; }"
        : "=r"(a) : "l"(p));
    return a;
}

#define CP_ASYNC16(sa, ga) \
    asm volatile("cp.async.cg.shared.global [%0], [%1], 16;" :: "r"((uint32_t)(sa)), "l"(ga))
#define CP_COMMIT() asm volatile("cp.async.commit_group;" ::: "memory")
#define CP_WAIT(n)  asm volatile("cp.async.wait_group %0;" :: "n"(n) : "memory")

__device__ __forceinline__ float round_tf32(float f) {
    uint32_t u;
    asm("cvt.rna.tf32.f32 %0, %1;" : "=r"(u) : "f"(f));
    return __uint_as_float(u);
}

__device__ __forceinline__ void mma_tf32(float* d,
                                         uint32_t a0, uint32_t a1,
                                         uint32_t a2, uint32_t a3,
                                         uint32_t b0, uint32_t b1) {
    asm volatile(
        "mma.sync.aligned.m16n8k8.row.col.f32.tf32.tf32.f32 "
        "{%0,%1,%2,%3}, {%4,%5,%6,%7}, {%8,%9}, {%0,%1,%2,%3};"
        : "+f"(d[0]), "+f"(d[1]), "+f"(d[2]), "+f"(d[3])
        : "r"(a0), "r"(a1), "r"(a2), "r"(a3), "r"(b0), "r"(b1));
}

__device__ __forceinline__ float gelu_exact(float v) {
    return 0.5f * v * (1.0f + erff(v * 0.70710678118654752f));
}

// ---------------------------------------------------------------------------
// fused tf32 rounding pass over 5 buffers (one launch)
// ---------------------------------------------------------------------------
__global__ void __launch_bounds__(256) round_all_kernel(
    const float4* __restrict__ i0, float4* __restrict__ o0, int n0,
    const float4* __restrict__ i1, float4* __restrict__ o1, int n1,
    const float4* __restrict__ i2, float4* __restrict__ o2, int n2,
    const float4* __restrict__ i3, float4* __restrict__ o3, int n3,
    const float4* __restrict__ i4, float4* __restrict__ o4, int n4)
{
    const int total = n0 + n1 + n2 + n3 + n4;
    const int stride = gridDim.x * 256;
    for (int i = blockIdx.x * 256 + threadIdx.x; i < total; i += stride) {
        const float4* src;
        float4* dst;
        int idx = i;
        if (idx < n0)                    { src = i0; dst = o0; }
        else if ((idx -= n0) < n1)       { src = i1; dst = o1; }
        else if ((idx -= n1) < n2)       { src = i2; dst = o2; }
        else if ((idx -= n2) < n3)       { src = i3; dst = o3; }
        else            { idx -= n3;       src = i4; dst = o4; }
        float4 v = src[idx];
        v.x = round_tf32(v.x); v.y = round_tf32(v.y);
        v.z = round_tf32(v.z); v.w = round_tf32(v.w);
        dst[idx] = v;
    }
}

// ---------------------------------------------------------------------------
// tf32 mma.sync GEMM (inputs pre-rounded; no in-loop cvt)
// CTA 128x128xBK32, 8 warps (4m x 2n), warp tile 32x64, m16n8k8.
// 2-stage cp.async double buffer; GSTRIDE=48 -> conflict-free LDS.128.
// KDIM templated; incremental global pointers.
// MMA order: per 2-wide n-group, s-sweep over 4 independent MMAs.
// __launch_bounds__(256,2) pins regs <= 128 -> 2 CTAs/SM (critical!).
// ---------------------------------------------------------------------------
#define GBM 128
#define GBN 128
#define GBK 32
#define GSTRIDE 48
#define GSTG_FLOATS ((GBM + GBN) * GSTRIDE)     // 12288 floats / stage
#define GEMM_SMEM (2 * GSTG_FLOATS * 4)         // 98304 bytes

template <bool GELU, bool RESID, bool ROUND, int KDIM>
__global__ void __launch_bounds__(256, 2) tgemm(
    const float* __restrict__ A, const float* __restrict__ B,
    const float* __restrict__ bias, const float* __restrict__ resid,
    float* __restrict__ C, int N)
{
    extern __shared__ float sm[];
    const int tid  = threadIdx.x;
    const int wid  = tid >> 5, lane = tid & 31;
    const int wm   = wid >> 1, wn = wid & 1;     // 4 x 2 warp grid
    const int g    = lane >> 2, tg = lane & 3;
    const int m0   = blockIdx.y * GBM;
    const int n0   = blockIdx.x * GBN;
    constexpr int NITER = KDIM / GBK;
    static_assert(NITER % 2 == 0, "NITER even");

    float acc[2][8][4];
    #pragma unroll
    for (int i = 0; i < 2; i++)
        #pragma unroll
        for (int j = 0; j < 8; j++)
            #pragma unroll
            for (int k = 0; k < 4; k++) acc[i][j][k] = 0.f;

    // loader lanes
    const int lr = tid >> 3;            // 0..31
    const int lc = (tid & 7) * 4;       // 0..28
    const float* aptr = A + (size_t)(m0 + lr) * KDIM + lc;
    const float* bptr = B + (size_t)(n0 + lr) * KDIM + lc;
    const uint32_t sa_st = smem_u32(sm) + (uint32_t)(lr * GSTRIDE + lc) * 4u;
    const uint32_t sb_st = sa_st + GBM * GSTRIDE * 4u;
    constexpr uint32_t STG_B = GSTG_FLOATS * 4u;   // stage byte offset

    auto load_chunk = [&](uint32_t stoff) {
        #pragma unroll
        for (int i = 0; i < 4; i++)
            CP_ASYNC16(sa_st + stoff + i * (32 * GSTRIDE * 4),
                       aptr + (size_t)i * 32 * KDIM);
        #pragma unroll
        for (int i = 0; i < 4; i++)
            CP_ASYNC16(sb_st + stoff + i * (32 * GSTRIDE * 4),
                       bptr + (size_t)i * 32 * KDIM);
        aptr += GBK; bptr += GBK;
    };

    // per-warp fragment base pointers (stage 0)
    const float* sAg = sm + (wm * 32 + g) * GSTRIDE + 4 * tg;
    const float* sBg = sm + GBM * GSTRIDE + (wn * 64 + g) * GSTRIDE + 4 * tg;

    auto compute = [&](int stf) {
        const float* sA = sAg + stf;
        const float* sB = sBg + stf;
        #pragma unroll
        for (int half = 0; half < 2; half++) {
            const int kb = half * 16;
            uint4 alo[2], ahi[2];
            #pragma unroll
            for (int mi = 0; mi < 2; mi++) {
                alo[mi] = *(const uint4*)&sA[(mi * 16) * GSTRIDE + kb];
                ahi[mi] = *(const uint4*)&sA[(mi * 16 + 8) * GSTRIDE + kb];
            }
            #pragma unroll
            for (int grp = 0; grp < 4; grp++) {
                uint4 bv[2];
                #pragma unroll
                for (int nn = 0; nn < 2; nn++)
                    bv[nn] = *(const uint4*)&sB[((grp * 2 + nn) * 8) * GSTRIDE + kb];
                // s = 0 sweep: 4 independent MMAs
                #pragma unroll
                for (int nn = 0; nn < 2; nn++)
                    #pragma unroll
                    for (int mi = 0; mi < 2; mi++)
                        mma_tf32(acc[mi][grp * 2 + nn],
                                 alo[mi].x, ahi[mi].x, alo[mi].y, ahi[mi].y,
                                 bv[nn].x, bv[nn].y);
                // s = 1 sweep: 4 independent MMAs
                #pragma unroll
                for (int nn = 0; nn < 2; nn++)
                    #pragma unroll
                    for (int mi = 0; mi < 2; mi++)
                        mma_tf32(acc[mi][grp * 2 + nn],
                                 alo[mi].z, ahi[mi].z, alo[mi].w, ahi[mi].w,
                                 bv[nn].z, bv[nn].w);
            }
        }
    };

    load_chunk(0); CP_COMMIT();

    #pragma unroll 1
    for (int j = 0; j < NITER; j += 2) {
        load_chunk(STG_B); CP_COMMIT();
        CP_WAIT(1);
        __syncthreads();
        compute(0);
        __syncthreads();
        if (j + 2 < NITER) load_chunk(0);
        CP_COMMIT();
        CP_WAIT(1);
        __syncthreads();
        compute(GSTG_FLOATS);
        __syncthreads();
    }

    // epilogue
    #pragma unroll
    for (int mi = 0; mi < 2; mi++) {
        #pragma unroll
        for (int rr = 0; rr < 2; rr++) {
            const int m = m0 + wm * 32 + mi * 16 + rr * 8 + g;
            float* crow = C + (size_t)m * N;
            const float* rrow = RESID ? (resid + (size_t)m * N) : nullptr;
            #pragma unroll
            for (int ni = 0; ni < 8; ni++) {
                const int n = n0 + wn * 64 + ni * 8 + 2 * tg;
                float ox = acc[mi][ni][rr * 2 + 0] + bias[n];
                float oy = acc[mi][ni][rr * 2 + 1] + bias[n + 1];
                if (RESID) { ox += rrow[n]; oy += rrow[n + 1]; }
                if (GELU)  { ox = gelu_exact(ox); oy = gelu_exact(oy); }
                if (ROUND) { ox = round_tf32(ox); oy = round_tf32(oy); }
                float2 o = make_float2(ox, oy);
                *(float2*)(crow + n) = o;
            }
        }
    }
}

// ---------------------------------------------------------------------------
// Banded causal attention, flash-style (fp32 SIMT). Output tf32-rounded.
// ---------------------------------------------------------------------------
#define QPAD 65
#define ATTN_SMEM ((3 * 64 * QPAD + 64 * 64 + 3 * 64 + 256) * 4)

__global__ void __launch_bounds__(256) attn_kernel(
    const float* __restrict__ qkv, float* __restrict__ ctx)
{
    extern __shared__ float smf[];
    float* Qs    = smf;
    float* Ks    = Qs + 64 * QPAD;
    float* Ps    = Ks + 64 * QPAD;
    float* Vs    = Ps + 64 * QPAD;
    float* row_m = Vs + 64 * 64;
    float* row_l = row_m + 64;
    float* row_a = row_l + 64;
    float* red   = row_a + 64;

    const int t  = threadIdx.x;
    const int bh = blockIdx.y;
    const int b  = bh >> 4, h = bh & 15;
    const int q0 = blockIdx.x * 64;
    const size_t base = (size_t)b * 1024 * 3072 + (size_t)h * 64;

    {
        const int r = t >> 2, c = (t & 3) * 16;
        #pragma unroll
        for (int cc = 0; cc < 16; cc += 4) {
            float4 v = *(const float4*)(qkv + base + (size_t)(q0 + r) * 3072 + c + cc);
            Qs[r * QPAD + c + cc + 0] = v.x * 0.125f;
            Qs[r * QPAD + c + cc + 1] = v.y * 0.125f;
            Qs[r * QPAD + c + cc + 2] = v.z * 0.125f;
            Qs[r * QPAD + c + cc + 3] = v.w * 0.125f;
        }
    }
    if (t < 64) { row_m[t] = -1e30f; row_l[t] = 0.f; }

    float acc[4][4];
    #pragma unroll
    for (int i = 0; i < 4; i++)
        #pragma unroll
        for (int j = 0; j < 4; j++) acc[i][j] = 0.f;

    const int qs = (t & 15) * 4;
    const int ds = (t >> 4) * 4;
    const int iq = (t >> 4) * 4;
    const int jk = (t & 15) * 4;
    const int i_row = t & 63, grp = t >> 6;

    const int kt_lo = (q0 >= WIN) ? ((q0 - (WIN - 1)) >> 6) : 0;
    const int kt_hi = q0 >> 6;

    for (int kt = kt_lo; kt <= kt_hi; kt++) {
        const int k0 = kt * 64;
        __syncthreads();
        {
            const int r = t >> 2, c = (t & 3) * 16;
            #pragma unroll
            for (int cc = 0; cc < 16; cc += 4) {
                float4 kv = *(const float4*)(qkv + base + (size_t)(k0 + r) * 3072 + 1024 + c + cc);
                Ks[r * QPAD + c + cc + 0] = kv.x;
                Ks[r * QPAD + c + cc + 1] = kv.y;
                Ks[r * QPAD + c + cc + 2] = kv.z;
                Ks[r * QPAD + c + cc + 3] = kv.w;
                float4 vv = *(const float4*)(qkv + base + (size_t)(k0 + r) * 3072 + 2048 + c + cc);
                *(float4*)&Vs[r * 64 + c + cc] = vv;
            }
        }
        __syncthreads();

        float s[4][4];
        #pragma unroll
        for (int i = 0; i < 4; i++)
            #pragma unroll
            for (int j = 0; j < 4; j++) s[i][j] = 0.f;
        #pragma unroll 8
        for (int d = 0; d < 64; d++) {
            float qf[4], kf[4];
            #pragma unroll
            for (int ii = 0; ii < 4; ii++) qf[ii] = Qs[(iq + ii) * QPAD + d];
            #pragma unroll
            for (int jj = 0; jj < 4; jj++) kf[jj] = Ks[(jk + jj) * QPAD + d];
            #pragma unroll
            for (int ii = 0; ii < 4; ii++)
                #pragma unroll
                for (int jj = 0; jj < 4; jj++)
                    s[ii][jj] = fmaf(qf[ii], kf[jj], s[ii][jj]);
        }
        #pragma unroll
        for (int ii = 0; ii < 4; ii++) {
            const int qi = q0 + iq + ii;
            #pragma unroll
            for (int jj = 0; jj < 4; jj++) {
                const int kj = k0 + jk + jj;
                const bool ok = (kj <= qi) && (qi - kj < WIN);
                Ps[(iq + ii) * QPAD + jk + jj] = ok ? s[ii][jj] : -1e30f;
            }
        }
        __syncthreads();

        {
            float pm = -1e30f;
            #pragma unroll
            for (int jj = 0; jj < 16; jj++)
                pm = fmaxf(pm, Ps[i_row * QPAD + grp * 16 + jj]);
            red[i_row * 4 + grp] = pm;
        }
        __syncthreads();
        if (t < 64) {
            const float mo = row_m[t];
            float mx = fmaxf(fmaxf(red[t * 4 + 0], red[t * 4 + 1]),
                             fmaxf(red[t * 4 + 2], red[t * 4 + 3]));
            mx = fmaxf(mx, mo);
            row_a[t] = expf(mo - mx);
            row_m[t] = mx;
        }
        __syncthreads();
        {
            const float m = row_m[i_row];
            float psum = 0.f;
            #pragma unroll
            for (int jj = 0; jj < 16; jj++) {
                const float sv = Ps[i_row * QPAD + grp * 16 + jj];
                const float p = (sv > -1e29f) ? expf(sv - m) : 0.f;
                Ps[i_row * QPAD + grp * 16 + jj] = p;
                psum += p;
            }
            red[i_row * 4 + grp] = psum;
        }
        __syncthreads();
        if (t < 64)
            row_l[t] = row_l[t] * row_a[t] +
                       red[t * 4 + 0] + red[t * 4 + 1] + red[t * 4 + 2] + red[t * 4 + 3];

        float al[4];
        #pragma unroll
        for (int qq = 0; qq < 4; qq++) al[qq] = row_a[qs + qq];
        #pragma unroll
        for (int qq = 0; qq < 4; qq++)
            #pragma unroll
            for (int dd = 0; dd < 4; dd++) acc[qq][dd] *= al[qq];

        #pragma unroll 8
        for (int jj = 0; jj < 64; jj++) {
            float4 v4 = *(const float4*)&Vs[jj * 64 + ds];
            float pf[4];
            #pragma unroll
            for (int qq = 0; qq < 4; qq++) pf[qq] = Ps[(qs + qq) * QPAD + jj];
            #pragma unroll
            for (int qq = 0; qq < 4; qq++) {
                acc[qq][0] = fmaf(pf[qq], v4.x, acc[qq][0]);
                acc[qq][1] = fmaf(pf[qq], v4.y, acc[qq][1]);
                acc[qq][2] = fmaf(pf[qq], v4.z, acc[qq][2]);
                acc[qq][3] = fmaf(pf[qq], v4.w, acc[qq][3]);
            }
        }
    }

    __syncthreads();
    #pragma unroll
    for (int qq = 0; qq < 4; qq++) {
        const float inv = 1.f / row_l[qs + qq];
        float4 o;
        o.x = round_tf32(acc[qq][0] * inv);
        o.y = round_tf32(acc[qq][1] * inv);
        o.z = round_tf32(acc[qq][2] * inv);
        o.w = round_tf32(acc[qq][3] * inv);
        *(float4*)(ctx + (size_t)(b * 1024 + q0 + qs + qq) * 1024 + h * 64 + ds) = o;
    }
}

// ---------------------------------------------------------------------------
// LayerNorm: optional second tf32-rounded output
// ---------------------------------------------------------------------------
__global__ void __launch_bounds__(256) ln_kernel(
    const float* __restrict__ in, const float* __restrict__ g,
    const float* __restrict__ be, float* __restrict__ out,
    float* __restrict__ out_r)
{
    __shared__ float red[8];
    __shared__ float s_mu, s_rs;
    const int t = threadIdx.x;
    const size_t row = blockIdx.x;

    float4 v = ((const float4*)(in + row * 1024))[t];
    float sum = v.x + v.y + v.z + v.w;
    #pragma unroll
    for (int o = 16; o; o >>= 1) sum += __shfl_xor_sync(~0u, sum, o);
    if ((t & 31) == 0) red[t >> 5] = sum;
    __syncthreads();
    if (t == 0) {
        float s = 0.f;
        #pragma unroll
        for (int i = 0; i < 8; i++) s += red[i];
        s_mu = s * (1.f / 1024.f);
    }
    __syncthreads();
    const float mu = s_mu;
    const float dx = v.x - mu, dy = v.y - mu, dz = v.z - mu, dw = v.w - mu;
    float sq = dx * dx + dy * dy + dz * dz + dw * dw;
    #pragma unroll
    for (int o = 16; o; o >>= 1) sq += __shfl_xor_sync(~0u, sq, o);
    __syncthreads();
    if ((t & 31) == 0) red[t >> 5] = sq;
    __syncthreads();
    if (t == 0) {
        float s = 0.f;
        #pragma unroll
        for (int i = 0; i < 8; i++) s += red[i];
        s_rs = rsqrtf(s * (1.f / 1024.f) + 1e-5f);
    }
    __syncthreads();
    const float rs = s_rs;
    float4 gv = ((const float4*)g)[t];
    float4 bv = ((const float4*)be)[t];
    float4 o;
    o.x = dx * rs * gv.x + bv.x;
    o.y = dy * rs * gv.y + bv.y;
    o.z = dz * rs * gv.z + bv.z;
    o.w = dw * rs * gv.w + bv.w;
    ((float4*)(out + row * 1024))[t] = o;
    if (out_r) {
        float4 r;
        r.x = round_tf32(o.x); r.y = round_tf32(o.y);
        r.z = round_tf32(o.z); r.w = round_tf32(o.w);
        ((float4*)(out_r + row * 1024))[t] = r;
    }
}

// ---------------------------------------------------------------------------
// launch
// ---------------------------------------------------------------------------
extern "C" void kernel_launch(void* const* d_in, const int* in_sizes, int n_in,
                              void* d_out, int out_size)
{
    const float* x    = (const float*)d_in[0];
    const float* Wqkv = (const float*)d_in[1];
    const float* bqkv = (const float*)d_in[2];
    const float* Wo   = (const float*)d_in[3];
    const float* bo   = (const float*)d_in[4];
    const float* W1   = (const float*)d_in[5];
    const float* b1   = (const float*)d_in[6];
    const float* W2   = (const float*)d_in[7];
    const float* b2   = (const float*)d_in[8];
    const float* g1   = (const float*)d_in[9];
    const float* be1  = (const float*)d_in[10];
    const float* g2   = (const float*)d_in[11];
    const float* be2  = (const float*)d_in[12];
    float* out = (float*)d_out;

    float *qkv, *ctx, *y, *x1, *x1r, *hb, *xr, *wqkvr, *wor, *w1r, *w2r;
    cudaGetSymbolAddress((void**)&qkv,   g_qkv);
    cudaGetSymbolAddress((void**)&ctx,   g_ctx);
    cudaGetSymbolAddress((void**)&y,     g_y);
    cudaGetSymbolAddress((void**)&x1,    g_x1);
    cudaGetSymbolAddress((void**)&x1r,   g_x1r);
    cudaGetSymbolAddress((void**)&hb,    g_h);
    cudaGetSymbolAddress((void**)&xr,    g_xr);
    cudaGetSymbolAddress((void**)&wqkvr, g_wqkvr);
    cudaGetSymbolAddress((void**)&wor,   g_wor);
    cudaGetSymbolAddress((void**)&w1r,   g_w1r);
    cudaGetSymbolAddress((void**)&w2r,   g_w2r);

    cudaFuncSetAttribute(attn_kernel,
                         cudaFuncAttributeMaxDynamicSharedMemorySize, ATTN_SMEM);
    cudaFuncSetAttribute((tgemm<false, false, false, 1024>),
                         cudaFuncAttributeMaxDynamicSharedMemorySize, GEMM_SMEM);
    cudaFuncSetAttribute((tgemm<false, true, false, 1024>),
                         cudaFuncAttributeMaxDynamicSharedMemorySize, GEMM_SMEM);
    cudaFuncSetAttribute((tgemm<true, false, true, 1024>),
                         cudaFuncAttributeMaxDynamicSharedMemorySize, GEMM_SMEM);
    cudaFuncSetAttribute((tgemm<false, true, false, 4096>),
                         cudaFuncAttributeMaxDynamicSharedMemorySize, GEMM_SMEM);

    dim3 thr(256);

    // 0) pre-round all GEMM inputs to tf32 bit patterns (single fused launch)
    round_all_kernel<<<2048, thr>>>(
        (const float4*)x,    (float4*)xr,    TOKENS * CDIM / 4,
        (const float4*)Wqkv, (float4*)wqkvr, 3 * CDIM * CDIM / 4,
        (const float4*)Wo,   (float4*)wor,   CDIM * CDIM / 4,
        (const float4*)W1,   (float4*)w1r,   FFDIM * CDIM / 4,
        (const float4*)W2,   (float4*)w2r,   CDIM * FFDIM / 4);

    // 1) QKV projection
    tgemm<false, false, false, 1024><<<dim3(3072 / GBN, TOKENS / GBM), thr, GEMM_SMEM>>>(
        xr, wqkvr, bqkv, nullptr, qkv, 3 * CDIM);
    // 2) banded attention (writes tf32-rounded ctx)
    attn_kernel<<<dim3(1024 / 64, 4 * 16), thr, ATTN_SMEM>>>(qkv, ctx);
    // 3) Wo + bias + residual(x exact)
    tgemm<false, true, false, 1024><<<dim3(CDIM / GBN, TOKENS / GBM), thr, GEMM_SMEM>>>(
        ctx, wor, bo, x, y, CDIM);
    // 4) LN1 -> x1 (exact) + x1r (rounded)
    ln_kernel<<<TOKENS, thr>>>(y, g1, be1, x1, x1r);
    // 5) W1 + bias + GELU (writes tf32-rounded h)
    tgemm<true, false, true, 1024><<<dim3(FFDIM / GBN, TOKENS / GBM), thr, GEMM_SMEM>>>(
        x1r, w1r, b1, nullptr, hb, FFDIM);
    // 6) W2 + bias + residual(x1 exact)
    tgemm<false, true, false, 4096><<<dim3(CDIM / GBN, TOKENS / GBM), thr, GEMM_SMEM>>>(
        hb, w2r, b2, x1, y, CDIM);
    // 7) LN2 -> out
    ln_kernel<<<TOKENS, thr>>>(y, g2, be2, out, nullptr);
}